// round 1
// baseline (speedup 1.0000x reference)
#include <cuda_runtime.h>
#include <math.h>

// Problem shape (fixed by the dataset): x[B=32, C=1, F=128, T=4096] fp32.
// out[B, C, T, F] fp32.
#define NB 32
#define NF 128
#define NT 4096
#define EPSF 1e-5f

__device__ __forceinline__ float flg2(float v) {
    float r; asm("lg2.approx.f32 %0, %1;" : "=f"(r) : "f"(v)); return r;
}
__device__ __forceinline__ float fex2(float v) {
    float r; asm("ex2.approx.f32 %0, %1;" : "=f"(r) : "f"(v)); return r;
}

// One warp per (b,f) row. Warp scans the EMA in chunks of 32 timesteps via a
// rescaled inclusive prefix sum:  m_j = s*c^j * P_j + c^(j+1) * carry,
// with P_j = sum_{i<=j} x_i * c^(-i).  Since c = 1-s, carry_init = x_0 makes
// m_0 == x_0 exactly (matches the reference's scan init).
// 32 warps/block cover 32 consecutive f of one b; a 32x32 smem tile transposes
// each chunk so output writes ([B,T,F] layout) are fully coalesced.
__global__ __launch_bounds__(1024, 1)
void pcen_kernel(const float* __restrict__ x,
                 const float* __restrict__ alpha,
                 const float* __restrict__ delta,
                 const float* __restrict__ rparam,
                 float* __restrict__ out)
{
    __shared__ float tile[2][32][33];

    const int wid  = threadIdx.x >> 5;
    const int lane = threadIdx.x & 31;
    const int b    = blockIdx.x >> 2;          // 4 f-groups of 32
    const int fg   = (blockIdx.x & 3) << 5;    // f base for this block
    const int f    = fg + wid;

    // Smoothing coefficient (compile-time foldable): t_val = 256
    const double sD = (sqrt(1.0 + 4.0 * 65536.0) - 1.0) / (2.0 * 65536.0);
    const float s = (float)sD;
    const float c = 1.0f - s;

    // Per-lane powers of c (computed once in double for accuracy)
    const double lc   = log((double)c);
    const float cpow  = (float)exp(lc * (double)lane);   // c^lane
    const float cinv  = (float)exp(-lc * (double)lane);  // c^-lane
    const float cpow1 = cpow * c;                        // c^(lane+1)
    const float scp   = s * cpow;                        // s * c^lane

    // Per-f parameters (one row per warp)
    const float a   = expf(alpha[f]);
    const float d   = expf(delta[f]);
    const float rr  = expf(rparam[f]);
    const float drr = fex2(rr * flg2(d));                // d^rr (same approx path)
    const float na  = -a;

    const long row = ((long)(b * NF + f)) * NT;

    // carry = m_{-1} = x_0  =>  m_0 = c*x_0 + s*x_0 = x_0
    float carry = __ldg(&x[row]);

    float xv = __ldg(&x[row + lane]);  // chunk 0 preload

    int buf = 0;
    for (int t0 = 0; t0 < NT; t0 += 32, buf ^= 1) {
        // --- EMA scan over this 32-chunk ---
        float z = xv * cinv;
        #pragma unroll
        for (int off = 1; off < 32; off <<= 1) {
            float n = __shfl_up_sync(0xffffffffu, z, off);
            if (lane >= off) z += n;
        }
        float m = fmaf(scp, z, cpow1 * carry);
        carry = __shfl_sync(0xffffffffu, m, 31);

        // --- PCEN pointwise ---
        float sm = fex2(na * flg2(m + EPSF));            // (eps+m)^(-a)
        float u  = fmaf(xv, sm, d);
        float p  = fex2(rr * flg2(u)) - drr;             // u^rr - d^rr

        // Prefetch next chunk before the barrier to overlap latency
        int tn = t0 + 32;
        float xnext = 0.0f;
        if (tn < NT) xnext = __ldg(&x[row + tn + lane]);

        // --- transpose via smem, coalesced write to [B,T,F] ---
        tile[buf][lane][wid] = p;
        __syncthreads();
        float v = tile[buf][wid][lane];
        out[((long)b * NT + (t0 + wid)) * NF + fg + lane] = v;

        xv = xnext;
    }
}

extern "C" void kernel_launch(void* const* d_in, const int* in_sizes, int n_in,
                              void* d_out, int out_size) {
    (void)in_sizes; (void)n_in; (void)out_size;
    const float* x     = (const float*)d_in[0];
    const float* alpha = (const float*)d_in[1];
    const float* delta = (const float*)d_in[2];
    const float* rpar  = (const float*)d_in[3];
    float* out = (float*)d_out;

    // 128 blocks (32 b * 4 f-groups), 1024 threads (32 warps, one per f row)
    pcen_kernel<<<NB * (NF / 32), 1024>>>(x, alpha, delta, rpar, out);
}

// round 3
// speedup vs baseline: 1.8095x; 1.8095x over previous
#include <cuda_runtime.h>
#include <math.h>

// x[B=32, C=1, F=128, T=4096] fp32 -> out[B, C, T, F] fp32 (PCEN).
#define NB 32
#define NF 128
#define NT 4096
#define EPSF 1e-5f

__device__ __forceinline__ float flg2(float v) {
    float r; asm("lg2.approx.f32 %0, %1;" : "=f"(r) : "f"(v)); return r;
}
__device__ __forceinline__ float fex2(float v) {
    float r; asm("ex2.approx.f32 %0, %1;" : "=f"(r) : "f"(v)); return r;
}

// One warp per (b,f) row. Chunk = 128 timesteps/iteration:
// each lane owns 4 consecutive t (float4 load), does a local zero-carry EMA,
// the warp scans only the 32 segment totals (rescaled by c^-4j), then each
// lane recombines its 4 values with pure FMAs. 32 iterations per row.
// Transpose via float4 smem tile -> 4 coalesced 128B output stores/thread.
__global__ __launch_bounds__(1024, 1)
void pcen_kernel(const float* __restrict__ x,
                 const float* __restrict__ alpha,
                 const float* __restrict__ delta,
                 const float* __restrict__ rparam,
                 float* __restrict__ out)
{
    __shared__ float4 tile4[2][32][33];

    const int wid  = threadIdx.x >> 5;
    const int lane = threadIdx.x & 31;
    const int b    = blockIdx.x >> 2;
    const int fg   = (blockIdx.x & 3) << 5;
    const int f    = fg + wid;

    // s from t_val = 256 (compile-time foldable)
    const double sD = (sqrt(1.0 + 4.0 * 65536.0) - 1.0) / (2.0 * 65536.0);
    const float s = (float)sD;
    const float c = 1.0f - s;
    const float c2 = c * c, c3 = c2 * c, c4 = c2 * c2;

    // Per-lane powers of c^4 (double precision at init)
    const double lc4   = 4.0 * log((double)c);
    const float c4pow  = (float)exp(lc4 * (double)lane);        // c^(4*lane)
    const float c4inv  = (float)exp(-lc4 * (double)lane);       // c^(-4*lane)
    const float c4powm1 = c4pow * (float)exp(-lc4);             // c^(4*(lane-1))
    const float c4pow1  = c4pow * c4;                           // c^(4*(lane+1))

    // Per-f parameters
    const float a   = expf(alpha[f]);
    const float d   = expf(delta[f]);
    const float rr  = expf(rparam[f]);
    const float drr = fex2(rr * flg2(d));
    const float na  = -a;

    const long row = ((long)(b * NF + f)) * NT;
    const float4* xrow = (const float4*)(x + row);

    // carry = m_{-1} = x_0  =>  m_0 = x_0 exactly
    float carry = __ldg(&x[row]);

    float4 xv = __ldg(&xrow[lane]);  // preload chunk 0

    int buf = 0;
    for (int t0 = 0; t0 < NT; t0 += 128, buf ^= 1) {
        // --- local zero-carry EMA over 4 elements ---
        float l0 = s * xv.x;
        float l1 = fmaf(c, l0, s * xv.y);
        float l2 = fmaf(c, l1, s * xv.z);
        float l3 = fmaf(c, l2, s * xv.w);

        // --- warp scan of segment totals (rescaled) ---
        float u = l3 * c4inv;
        #pragma unroll
        for (int off = 1; off < 32; off <<= 1) {
            float n = __shfl_up_sync(0xffffffffu, u, off);
            if (lane >= off) u += n;
        }
        // carry into this lane's segment (m at t = t0+4*lane-1)
        float uprev = __shfl_up_sync(0xffffffffu, u, 1);
        float Min = (lane == 0) ? carry
                                : fmaf(c4powm1, uprev, c4pow * carry);
        // next chunk's carry = M_31
        float Mend = fmaf(c4pow, u, c4pow1 * carry);
        carry = __shfl_sync(0xffffffffu, Mend, 31);

        // --- recombine: m_k = l_k + c^(k+1) * Min ---
        float m0 = fmaf(c,  Min, l0);
        float m1 = fmaf(c2, Min, l1);
        float m2 = fmaf(c3, Min, l2);
        float m3 = fmaf(c4, Min, l3);

        // --- PCEN pointwise (4 independent chains) ---
        float p0 = fex2(rr * flg2(fmaf(xv.x, fex2(na * flg2(m0 + EPSF)), d))) - drr;
        float p1 = fex2(rr * flg2(fmaf(xv.y, fex2(na * flg2(m1 + EPSF)), d))) - drr;
        float p2 = fex2(rr * flg2(fmaf(xv.z, fex2(na * flg2(m2 + EPSF)), d))) - drr;
        float p3 = fex2(rr * flg2(fmaf(xv.w, fex2(na * flg2(m3 + EPSF)), d))) - drr;

        // prefetch next chunk before the barrier
        int tn4 = (t0 >> 2) + 32;  // next chunk index in float4 units
        float4 xnext = make_float4(0.f, 0.f, 0.f, 0.f);
        if (t0 + 128 < NT) xnext = __ldg(&xrow[tn4 + lane]);

        // --- transpose via float4 smem tile ---
        tile4[buf][lane][wid] = make_float4(p0, p1, p2, p3);
        __syncthreads();
        float4 v = tile4[buf][wid][lane];
        // thread (wid,lane) writes t = t0 + 4*wid + k, f = fg + lane
        long obase = ((long)b * NT + t0 + 4 * wid) * NF + fg + lane;
        out[obase]          = v.x;
        out[obase + NF]     = v.y;
        out[obase + 2 * NF] = v.z;
        out[obase + 3 * NF] = v.w;

        xv = xnext;
    }
}

extern "C" void kernel_launch(void* const* d_in, const int* in_sizes, int n_in,
                              void* d_out, int out_size) {
    (void)in_sizes; (void)n_in; (void)out_size;
    const float* x     = (const float*)d_in[0];
    const float* alpha = (const float*)d_in[1];
    const float* delta = (const float*)d_in[2];
    const float* rpar  = (const float*)d_in[3];
    float* out = (float*)d_out;

    pcen_kernel<<<NB * (NF / 32), 1024>>>(x, alpha, delta, rpar, out);
}

// round 4
// speedup vs baseline: 1.9015x; 1.0508x over previous
#include <cuda_runtime.h>
#include <math.h>

// x[B=32, C=1, F=128, T=4096] fp32 -> out[B, C, T, F] fp32 (PCEN).
#define NB 32
#define NF 128
#define NT 4096
#define EPSF 1e-5f
#define NITER 16            // NT / 256
#define SMEM_BYTES (2 * 2 * 32 * 33 * 16)   // double-buffered 2-half float4 tile

__device__ __forceinline__ float flg2(float v) {
    float r; asm("lg2.approx.f32 %0, %1;" : "=f"(r) : "f"(v)); return r;
}
__device__ __forceinline__ float fex2(float v) {
    float r; asm("ex2.approx.f32 %0, %1;" : "=f"(r) : "f"(v)); return r;
}

// One warp per (b,f) row. Chunk = 256 timesteps/iteration:
// each lane owns 8 consecutive t (2 float4 loads), local zero-carry EMA over
// 8 elems, warp-scan of the 32 segment totals (rescaled by c^-8j, max 2.63),
// recombine with pure FMAs. 16 iterations per row; 16 block barriers total
// (double-buffered transpose tile in dynamic smem).
__global__ __launch_bounds__(1024, 1)
void pcen_kernel(const float* __restrict__ x,
                 const float* __restrict__ alpha,
                 const float* __restrict__ delta,
                 const float* __restrict__ rparam,
                 float* __restrict__ out)
{
    extern __shared__ float4 tile4[];   // [buf:2][half:2][32][33]
#define TILE(bf, h, i, j) tile4[((((bf) * 2 + (h)) * 32 + (i)) * 33) + (j)]

    const int wid  = threadIdx.x >> 5;
    const int lane = threadIdx.x & 31;
    const int b    = blockIdx.x >> 2;
    const int fg   = (blockIdx.x & 3) << 5;
    const int f    = fg + wid;

    // s from t_val = 256 (compile-time foldable)
    const double sD = (sqrt(1.0 + 4.0 * 65536.0) - 1.0) / (2.0 * 65536.0);
    const float s = (float)sD;
    const float c  = 1.0f - s;
    const float c2 = c * c,  c3 = c2 * c,  c4 = c2 * c2;
    const float c5 = c4 * c, c6 = c4 * c2, c7 = c4 * c3, c8 = c4 * c4;

    // Per-lane powers of c^8 (double precision at init)
    const double lc8    = 8.0 * log((double)c);
    const float c8pow   = (float)exp(lc8 * (double)lane);    // c^(8*lane)
    const float c8inv   = (float)exp(-lc8 * (double)lane);   // c^(-8*lane)
    const float c8powm1 = c8pow * (float)exp(-lc8);          // c^(8*(lane-1))
    const float c8pow1  = c8pow * c8;                        // c^(8*(lane+1))

    // Per-f parameters
    const float a   = expf(alpha[f]);
    const float d   = expf(delta[f]);
    const float rr  = expf(rparam[f]);
    const float drr = fex2(rr * flg2(d));
    const float na  = -a;

    const long row = ((long)(b * NF + f)) * NT;
    const float4* xrow = (const float4*)(x + row);

    // carry = m_{-1} = x_0  =>  m_0 = x_0 exactly
    float carry = __ldg(&x[row]);

    // preload chunk 0: lane owns float4s [2*lane, 2*lane+1]
    float4 xv0 = __ldg(&xrow[2 * lane]);
    float4 xv1 = __ldg(&xrow[2 * lane + 1]);

    int buf = 0;
    for (int it = 0; it < NITER; ++it, buf ^= 1) {
        // --- local zero-carry EMA over 8 elements ---
        float l0 = s * xv0.x;
        float l1 = fmaf(c, l0, s * xv0.y);
        float l2 = fmaf(c, l1, s * xv0.z);
        float l3 = fmaf(c, l2, s * xv0.w);
        float l4 = fmaf(c, l3, s * xv1.x);
        float l5 = fmaf(c, l4, s * xv1.y);
        float l6 = fmaf(c, l5, s * xv1.z);
        float l7 = fmaf(c, l6, s * xv1.w);

        // --- warp scan of segment totals (rescaled) ---
        float u = l7 * c8inv;
        #pragma unroll
        for (int off = 1; off < 32; off <<= 1) {
            float n = __shfl_up_sync(0xffffffffu, u, off);
            if (lane >= off) u += n;
        }
        float uprev = __shfl_up_sync(0xffffffffu, u, 1);
        float Min = (lane == 0) ? carry
                                : fmaf(c8powm1, uprev, c8pow * carry);
        float Mend = fmaf(c8pow, u, c8pow1 * carry);
        carry = __shfl_sync(0xffffffffu, Mend, 31);

        // --- recombine + PCEN pointwise (8 independent chains) ---
        float m0 = fmaf(c,  Min, l0), m1 = fmaf(c2, Min, l1);
        float m2 = fmaf(c3, Min, l2), m3 = fmaf(c4, Min, l3);
        float m4 = fmaf(c5, Min, l4), m5 = fmaf(c6, Min, l5);
        float m6 = fmaf(c7, Min, l6), m7 = fmaf(c8, Min, l7);

        float p0 = fex2(rr * flg2(fmaf(xv0.x, fex2(na * flg2(m0 + EPSF)), d))) - drr;
        float p1 = fex2(rr * flg2(fmaf(xv0.y, fex2(na * flg2(m1 + EPSF)), d))) - drr;
        float p2 = fex2(rr * flg2(fmaf(xv0.z, fex2(na * flg2(m2 + EPSF)), d))) - drr;
        float p3 = fex2(rr * flg2(fmaf(xv0.w, fex2(na * flg2(m3 + EPSF)), d))) - drr;
        float p4 = fex2(rr * flg2(fmaf(xv1.x, fex2(na * flg2(m4 + EPSF)), d))) - drr;
        float p5 = fex2(rr * flg2(fmaf(xv1.y, fex2(na * flg2(m5 + EPSF)), d))) - drr;
        float p6 = fex2(rr * flg2(fmaf(xv1.z, fex2(na * flg2(m6 + EPSF)), d))) - drr;
        float p7 = fex2(rr * flg2(fmaf(xv1.w, fex2(na * flg2(m7 + EPSF)), d))) - drr;

        // stage into transpose tile
        TILE(buf, 0, lane, wid) = make_float4(p0, p1, p2, p3);
        TILE(buf, 1, lane, wid) = make_float4(p4, p5, p6, p7);

        // unconditional prefetch of next chunk (clamped to chunk 0 on last iter)
        int nb4 = (it + 1 < NITER) ? (it + 1) * 64 : 0;
        xv0 = __ldg(&xrow[nb4 + 2 * lane]);
        xv1 = __ldg(&xrow[nb4 + 2 * lane + 1]);

        __syncthreads();

        // read transposed: thread (wid,lane) -> t = t0 + 8*wid + 4h + k, f = fg+lane
        float4 v0 = TILE(buf, 0, wid, lane);
        float4 v1 = TILE(buf, 1, wid, lane);
        long obase = ((long)b * NT + (long)it * 256 + 8 * wid) * NF + fg + lane;
        out[obase]          = v0.x;
        out[obase + NF]     = v0.y;
        out[obase + 2 * NF] = v0.z;
        out[obase + 3 * NF] = v0.w;
        out[obase + 4 * NF] = v1.x;
        out[obase + 5 * NF] = v1.y;
        out[obase + 6 * NF] = v1.z;
        out[obase + 7 * NF] = v1.w;
    }
#undef TILE
}

extern "C" void kernel_launch(void* const* d_in, const int* in_sizes, int n_in,
                              void* d_out, int out_size) {
    (void)in_sizes; (void)n_in; (void)out_size;
    const float* x     = (const float*)d_in[0];
    const float* alpha = (const float*)d_in[1];
    const float* delta = (const float*)d_in[2];
    const float* rpar  = (const float*)d_in[3];
    float* out = (float*)d_out;

    // Raise dynamic smem cap (67.6KB > 48KB default). Host-side, not an
    // allocation, not a stream op — graph-capture safe; idempotent per call.
    cudaFuncSetAttribute(pcen_kernel,
                         cudaFuncAttributeMaxDynamicSharedMemorySize,
                         SMEM_BYTES);

    pcen_kernel<<<NB * (NF / 32), 1024, SMEM_BYTES>>>(x, alpha, delta, rpar, out);
}